// round 14
// baseline (speedup 1.0000x reference)
#include <cuda_runtime.h>
#include <math.h>

#define NRES 768
#define BATCH 2
#define KTOP 30
#define DP 128
#define INFV 1e10f
#define NE   (BATCH*NRES)    // 1536 embed sites
#define NGRP 384             // groups of 6 blocks: 4 embed + 2 relpos (2 sites each)

typedef unsigned long long ull;

__device__ __forceinline__ ull fma2(ull a, ull b, ull c){
    ull d; asm("fma.rn.f32x2 %0, %1, %2, %3;" : "=l"(d) : "l"(a), "l"(b), "l"(c)); return d;
}
__device__ __forceinline__ ull packdup(float x){
    ull r; asm("mov.b64 %0, {%1, %2};" : "=l"(r) : "f"(x), "f"(x)); return r;
}
__device__ __forceinline__ void unpack2(ull v, float& lo, float& hi){
    asm("mov.b64 {%0, %1}, %2;" : "=f"(lo), "=f"(hi) : "l"(v));
}
// gelu tanh-approximate, exp-based
__device__ __forceinline__ float gelu_t(float x){
    float u = x + 0.044715f*x*x*x;
    float a = fabsf(u);
    float en = __expf(-1.5957691216057308f*a);
    float t = 1.0f - __fdividef(2.0f*en, 1.0f + en);
    return 0.5f*x*(1.0f + copysignf(t, u));
}
__device__ __forceinline__ unsigned okey(float v){
    unsigned u = __float_as_uint(v);
    return (u & 0x80000000u) ? ~u : (u | 0x80000000u);
}
__device__ __forceinline__ ull umin64(ull a, ull b){ return a < b ? a : b; }
__device__ __forceinline__ unsigned smem_u32(const void* p){
    unsigned a;
    asm("{ .reg .u64 t; cvta.to.shared.u64 t, %1; cvt.u32.u64 %0, t; }" : "=r"(a) : "l"(p));
    return a;
}
__device__ __forceinline__ void bulk_cp(void* dst, unsigned src_sm, unsigned bytes){
    asm volatile("cp.async.bulk.global.shared::cta.bulk_group [%0], [%1], %2;"
                 :: "l"(dst), "r"(src_sm), "r"(bytes) : "memory");
}

union F4 { float4 v; ull u[2]; };

struct SmemE {
    ull   h2[DP*16];      // 16 KB
    ull   keys[NRES];     // 6 KB
    float dists[NRES];    // 3 KB
    float w1aT[DP][8];    // 4 KB: [d] = {w0..w4, b1a, 0, 0}
    float w1dT[DP][4];    // 2 KB: [d] = {w0, w1, w2, b1d}
    float b2a[DP], b2d[DP];
    float fe[6][32];
    float tiRi[12];
};
struct SmemR {
    float T[65*DP];       // 33.3 KB relpos table (TMA + STG source)
    float sv[256];
};

__device__ __forceinline__ void embed_role(
    unsigned char* smraw, int site,
    const int* __restrict__ ri, const float* __restrict__ frames, const float* __restrict__ smask,
    const float* __restrict__ Wa1, const float* __restrict__ ba1,
    const float* __restrict__ Wa2, const float* __restrict__ ba2,
    const float* __restrict__ Wd1, const float* __restrict__ bd1,
    const float* __restrict__ Wd2, const float* __restrict__ bd2,
    float* __restrict__ out_ang, float* __restrict__ out_dst)
{
    SmemE& S = *reinterpret_cast<SmemE*>(smraw);
    const int tid = threadIdx.x;
    const int b  = site / NRES;
    const int i  = site - b*NRES;

    for (int d = tid; d < DP; d += 256){
        #pragma unroll
        for (int j = 0; j < 5; j++) S.w1aT[d][j] = Wa1[j*DP + d];
        S.w1aT[d][5] = ba1[d]; S.w1aT[d][6] = 0.f; S.w1aT[d][7] = 0.f;
        #pragma unroll
        for (int j = 0; j < 3; j++) S.w1dT[d][j] = Wd1[j*DP + d];
        S.w1dT[d][3] = bd1[d];
    }
    if (tid < DP){ S.b2a[tid]=ba2[tid]; S.b2d[tid]=bd2[tid]; }
    if (tid < 3) S.tiRi[tid] = frames[(size_t)(b*NRES+i)*16 + tid*4 + 3];
    if (tid >= 32 && tid < 41){
        int e = tid - 32;
        S.tiRi[3+e] = frames[(size_t)(b*NRES+i)*16 + (e/3)*4 + (e%3)];
    }
    __syncthreads();

    const float ti0 = S.tiRi[0], ti1 = S.tiRi[1], ti2 = S.tiRi[2];
    const int   rii = ri[b*NRES + i];
    const float mi  = smask[b*NRES + i];

    #pragma unroll
    for (int e = 0; e < 3; e++){
        int j = tid*3 + e;
        const float* fj = frames + (size_t)(b*NRES + j)*16;
        float dx = fj[3]-ti0, dy = fj[7]-ti1, dz = fj[11]-ti2;
        float d = sqrtf(dx*dx + dy*dy + dz*dz);
        S.dists[j] = d;
        bool conn = abs(rii - ri[b*NRES + j]) == 1;
        bool m = (mi != 0.f) && (smask[b*NRES + j] != 0.f);
        float v = conn ? -INFV : (!m ? INFV : ((j == i) ? INFV : d));
        S.keys[j] = ((ull)okey(v) << 32) | (unsigned)j;
    }
    __syncthreads();

    if (tid < 32){
        const int lane = tid;
        ull mymin = ~0ull;
        #pragma unroll
        for (int e = 0; e < 24; e++) mymin = umin64(mymin, S.keys[e*32 + lane]);
        int mysel = -1;
        for (int it = 0; it < KTOP; it++){
            ull m = mymin;
            #pragma unroll
            for (int off = 16; off; off >>= 1)
                m = umin64(m, __shfl_xor_sync(0xffffffffu, m, off));
            if (it == lane) mysel = (int)(m & 0xffffffffu);
            if (m == mymin){
                S.keys[(int)(m & 0xffffffffu)] = ~0ull;
                ull t = ~0ull;
                #pragma unroll
                for (int e = 0; e < 24; e++) t = umin64(t, S.keys[e*32 + lane]);
                mymin = t;
            }
        }
        __syncwarp();
        if (lane < KTOP){
            int sel = mysel;
            const float* fj = frames + (size_t)(b*NRES + sel)*16;
            float dx = fj[3]-ti0, dy = fj[7]-ti1, dz = fj[11]-ti2;
            float d = S.dists[sel];
            float inv = (d > 0.f) ? (1.0f/d) : 0.f;
            float tr0 = S.tiRi[3+0]*dx + S.tiRi[3+3]*dy + S.tiRi[3+6]*dz;
            float tr1 = S.tiRi[3+1]*dx + S.tiRi[3+4]*dy + S.tiRi[3+7]*dz;
            float tr2 = S.tiRi[3+2]*dx + S.tiRi[3+5]*dy + S.tiRi[3+8]*dz;
            S.fe[0][lane] = (sel == i) ? 1.f : 0.f;
            S.fe[1][lane] = (abs(rii - ri[b*NRES + sel]) == 1) ? 1.f : 0.f;
            S.fe[2][lane] = tr0*inv;
            S.fe[3][lane] = tr1*inv;
            S.fe[4][lane] = tr2*inv;
            S.fe[5][lane] = d;
        } else {
            #pragma unroll
            for (int f = 0; f < 6; f++) S.fe[f][lane] = 0.f;
        }
    }
    __syncthreads();

    const int kk = tid & 31;
    const float f0 = S.fe[0][kk], f1 = S.fe[1][kk], f2 = S.fe[2][kk];
    const float f3 = S.fe[3][kk], f4 = S.fe[4][kk], f5 = S.fe[5][kk];
    const bool kval = (kk < KTOP);

    const int rg   = tid >> 6;           // 4 row groups (4 pairs = 8 rows)
    const int cg   = (tid >> 5) & 1;     // col half
    const int lane = tid & 31;
    const int col0 = cg*64 + lane*2;     // 2 adjacent cols per lane
    const ull* hp  = S.h2 + rg*4;
    const size_t base = (size_t)site * KTOP * DP;

    #pragma unroll
    for (int emb = 0; emb < 2; emb++){
        #pragma unroll
        for (int it = 0; it < 16; it++){
            int d = (tid >> 5) + 8*it;
            float h = 0.f;
            if (kval){
                float pre;
                if (emb == 0){
                    float4 wa = ((const float4*)S.w1aT[d])[0];
                    float4 wb = ((const float4*)S.w1aT[d])[1];
                    pre = wb.y + f0*wa.x + f1*wa.y + f2*wa.z + f3*wa.w + f4*wb.x;
                } else {
                    float4 wd = ((const float4*)S.w1dT[d])[0];
                    pre = wd.w + f0*wd.x + f1*wd.y + f5*wd.z;
                }
                h = gelu_t(pre);
            }
            ((float*)S.h2)[d*32 + kk] = h;
        }
        __syncthreads();

        const float* __restrict__ Wg = (emb ? Wd2 : Wa2) + col0;
        ull a00=0,a10=0,a20=0,a30=0, a01=0,a11=0,a21=0,a31=0;
        #pragma unroll 4
        for (int d = 0; d < DP; d++){
            F4 x0, x1;
            x0.v = ((const float4*)(hp + d*16))[0];
            x1.v = ((const float4*)(hp + d*16 + 2))[0];
            float2 w2v = *(const float2*)(Wg + d*DP);
            ull wxa = packdup(w2v.x);
            ull wxb = packdup(w2v.y);
            a00 = fma2(x0.u[0], wxa, a00); a10 = fma2(x0.u[1], wxa, a10);
            a20 = fma2(x1.u[0], wxa, a20); a30 = fma2(x1.u[1], wxa, a30);
            a01 = fma2(x0.u[0], wxb, a01); a11 = fma2(x0.u[1], wxb, a11);
            a21 = fma2(x1.u[0], wxb, a21); a31 = fma2(x1.u[1], wxb, a31);
        }
        const float* b2 = emb ? S.b2d : S.b2a;
        float bv0 = b2[col0], bv1 = b2[col0 + 1];
        float* __restrict__ og = emb ? out_dst : out_ang;
        ull accA[4] = {a00, a10, a20, a30};
        ull accB[4] = {a01, a11, a21, a31};
        #pragma unroll
        for (int p = 0; p < 4; p++){
            int r0 = rg*8 + 2*p;
            float lo, hi, lo2, hi2;
            unpack2(accA[p], lo, hi);
            unpack2(accB[p], lo2, hi2);
            if (r0 < KTOP)
                *(float2*)(og + base + (size_t)r0*DP + col0) = make_float2(lo + bv0, lo2 + bv1);
            if (r0 + 1 < KTOP)
                *(float2*)(og + base + (size_t)(r0+1)*DP + col0) = make_float2(hi + bv0, hi2 + bv1);
        }
        if (emb == 0) __syncthreads();
    }
}

// relpos: block = 2 sites. 62.5% TMA / 37.5% STG:
// site A fully TMA (768 rows); site B rows [0,192) TMA, rows [192,768) STG.128
// issued between commit and wait (warps otherwise idle during engine drain).
__device__ __forceinline__ void relpos_role(
    unsigned char* smraw, int g,
    const int* __restrict__ ri,
    const float* __restrict__ W_rp, const float* __restrict__ b_rp,
    const float* __restrict__ W_tf, const float* __restrict__ b_tf,
    float* __restrict__ out_s, float* __restrict__ out_rp)
{
    SmemR& S = *reinterpret_cast<SmemR*>(smraw);
    const int tid = threadIdx.x;
    for (int e = tid; e < 65*DP; e += 256) S.T[e] = W_rp[e] + b_rp[e & 127];
    S.sv[tid] = W_tf[tid] + b_tf[tid];
    asm volatile("fence.proxy.async.shared::cta;" ::: "memory");
    __syncthreads();

    // s: 768 relpos blocks x 128 float4 = full (2,768,256)
    if (tid < 128)
        ((float4*)out_s)[g*128 + tid] = ((const float4*)S.sv)[tid & 63];

    const unsigned tsm = smem_u32(S.T);
    const int siteA = g*2, siteB = g*2 + 1;
    const int bb  = siteA / NRES;                 // both sites same batch (NRES even)
    const int iA  = siteA - bb*NRES;
    const int iB  = iA + 1;
    const int riA = ri[bb*NRES + iA];
    const int riB = ri[bb*NRES + iB];
    const int* __restrict__ rj = ri + bb*NRES;
    float* __restrict__ dstA = out_rp + (size_t)siteA * NRES * DP;
    float* __restrict__ dstB = out_rp + (size_t)siteB * NRES * DP;

    // site A: all 768 rows via TMA
    #pragma unroll
    for (int e = 0; e < 3; e++){
        int j = tid + e*256;
        int d = min(32, max(-32, riA - rj[j])) + 32;
        bulk_cp(dstA + (size_t)j*DP, tsm + (unsigned)d*512u, 512u);
    }
    // site B rows [0,192) via TMA
    if (tid < 192){
        int j = tid;
        int d = min(32, max(-32, riB - rj[j])) + 32;
        bulk_cp(dstB + (size_t)j*DP, tsm + (unsigned)d*512u, 512u);
    }
    asm volatile("cp.async.bulk.commit_group;" ::: "memory");

    // site B rows [192,768) via STG.128 while the TMA engine drains (72 rows/warp)
    {
        const int lane = tid & 31;
        const int w    = tid >> 5;
        const float4* __restrict__ T4 = ((const float4*)S.T) + lane;
        float4* __restrict__ dst4 = ((float4*)dstB) + lane;
        int prevd = -1;
        float4 v;
        const int j0 = 192 + w*72;
        #pragma unroll 4
        for (int t = 0; t < 72; t++){
            int j = j0 + t;
            int d = min(32, max(-32, riB - rj[j])) + 32;
            if (d != prevd){ v = T4[d*32]; prevd = d; }
            dst4[(size_t)j*32] = v;
        }
    }
    asm volatile("cp.async.bulk.wait_group 0;" ::: "memory");
    __syncthreads();
}

__global__ __launch_bounds__(256, 5) void fused_kernel(
    const int* __restrict__ ri, const float* __restrict__ frames, const float* __restrict__ smask,
    const float* __restrict__ W_tf, const float* __restrict__ b_tf,
    const float* __restrict__ Wa1, const float* __restrict__ ba1,
    const float* __restrict__ Wa2, const float* __restrict__ ba2,
    const float* __restrict__ Wd1, const float* __restrict__ bd1,
    const float* __restrict__ Wd2, const float* __restrict__ bd2,
    const float* __restrict__ W_rp, const float* __restrict__ b_rp,
    float* __restrict__ out_s, float* __restrict__ out_ang,
    float* __restrict__ out_dst, float* __restrict__ out_rp)
{
    extern __shared__ unsigned char smraw[];
    const int bx  = blockIdx.x;
    const int grp = bx / 6;
    const int sub = bx - grp*6;
    if (sub < 4){
        embed_role(smraw, grp*4 + sub, ri, frames, smask,
                   Wa1, ba1, Wa2, ba2, Wd1, bd1, Wd2, bd2, out_ang, out_dst);
    } else {
        relpos_role(smraw, grp*2 + (sub - 4), ri, W_rp, b_rp, W_tf, b_tf, out_s, out_rp);
    }
}

extern "C" void kernel_launch(void* const* d_in, const int* in_sizes, int n_in,
                              void* d_out, int out_size)
{
    const int*   ri     = (const int*)  d_in[1];
    const float* frames = (const float*)d_in[2];
    const float* smaskp = (const float*)d_in[3];
    const float* W_tf   = (const float*)d_in[4];
    const float* b_tf   = (const float*)d_in[5];
    const float* Wa1    = (const float*)d_in[6];
    const float* ba1    = (const float*)d_in[7];
    const float* Wa2    = (const float*)d_in[8];
    const float* ba2    = (const float*)d_in[9];
    const float* Wd1    = (const float*)d_in[10];
    const float* bd1    = (const float*)d_in[11];
    const float* Wd2    = (const float*)d_in[12];
    const float* bd2    = (const float*)d_in[13];
    const float* W_rp   = (const float*)d_in[14];
    const float* b_rp   = (const float*)d_in[15];

    float* out     = (float*)d_out;
    float* out_s   = out;                                       // (2,768,256)
    float* out_ang = out_s   + (size_t)BATCH*NRES*256;          // (2,768,30,128)
    float* out_dst = out_ang + (size_t)BATCH*NRES*KTOP*DP;      // (2,768,30,128)
    float* out_rp  = out_dst + (size_t)BATCH*NRES*KTOP*DP;      // (2,768,768,128)

    int smem = (int)(sizeof(SmemE) > sizeof(SmemR) ? sizeof(SmemE) : sizeof(SmemR));
    cudaFuncSetAttribute(fused_kernel, cudaFuncAttributeMaxDynamicSharedMemorySize, smem);

    fused_kernel<<<NGRP*6, 256, smem>>>(
        ri, frames, smaskp, W_tf, b_tf,
        Wa1, ba1, Wa2, ba2, Wd1, bd1, Wd2, bd2, W_rp, b_rp,
        out_s, out_ang, out_dst, out_rp);
}

// round 15
// speedup vs baseline: 1.0004x; 1.0004x over previous
#include <cuda_runtime.h>
#include <math.h>

#define NRES 768
#define BATCH 2
#define KTOP 30
#define DP 128
#define INFV 1e10f
#define NE   (BATCH*NRES)    // 1536 embed sites
#define NGRP 384             // groups of 6 blocks: 4 embed + 2 relpos (2 sites each)

typedef unsigned long long ull;

__device__ __forceinline__ ull fma2(ull a, ull b, ull c){
    ull d; asm("fma.rn.f32x2 %0, %1, %2, %3;" : "=l"(d) : "l"(a), "l"(b), "l"(c)); return d;
}
__device__ __forceinline__ ull packdup(float x){
    ull r; asm("mov.b64 %0, {%1, %2};" : "=l"(r) : "f"(x), "f"(x)); return r;
}
__device__ __forceinline__ void unpack2(ull v, float& lo, float& hi){
    asm("mov.b64 {%0, %1}, %2;" : "=f"(lo), "=f"(hi) : "l"(v));
}
// gelu tanh-approximate, exp-based
__device__ __forceinline__ float gelu_t(float x){
    float u = x + 0.044715f*x*x*x;
    float a = fabsf(u);
    float en = __expf(-1.5957691216057308f*a);
    float t = 1.0f - __fdividef(2.0f*en, 1.0f + en);
    return 0.5f*x*(1.0f + copysignf(t, u));
}
__device__ __forceinline__ unsigned okey(float v){
    unsigned u = __float_as_uint(v);
    return (u & 0x80000000u) ? ~u : (u | 0x80000000u);
}
__device__ __forceinline__ ull umin64(ull a, ull b){ return a < b ? a : b; }
__device__ __forceinline__ unsigned smem_u32(const void* p){
    unsigned a;
    asm("{ .reg .u64 t; cvta.to.shared.u64 t, %1; cvt.u32.u64 %0, t; }" : "=r"(a) : "l"(p));
    return a;
}
__device__ __forceinline__ void bulk_cp(void* dst, unsigned src_sm, unsigned bytes){
    asm volatile("cp.async.bulk.global.shared::cta.bulk_group [%0], [%1], %2;"
                 :: "l"(dst), "r"(src_sm), "r"(bytes) : "memory");
}

union F4 { float4 v; ull u[2]; };

struct SmemE {
    ull   h2[DP*16];      // 16 KB
    ull   keys[NRES];     // 6 KB
    float dists[NRES];    // 3 KB
    float w1aT[DP][8];    // 4 KB: [d] = {w0..w4, b1a, 0, 0}
    float w1dT[DP][4];    // 2 KB: [d] = {w0, w1, w2, b1d}
    float b2a[DP], b2d[DP];
    float fe[6][32];
    float tiRi[12];
};
struct SmemR {
    float T[65*DP];       // 33.3 KB relpos table (TMA + STG source)
    float sv[256];
};

__device__ __forceinline__ void embed_role(
    unsigned char* smraw, int site,
    const int* __restrict__ ri, const float* __restrict__ frames, const float* __restrict__ smask,
    const float* __restrict__ Wa1, const float* __restrict__ ba1,
    const float* __restrict__ Wa2, const float* __restrict__ ba2,
    const float* __restrict__ Wd1, const float* __restrict__ bd1,
    const float* __restrict__ Wd2, const float* __restrict__ bd2,
    float* __restrict__ out_ang, float* __restrict__ out_dst)
{
    SmemE& S = *reinterpret_cast<SmemE*>(smraw);
    const int tid = threadIdx.x;
    const int b  = site / NRES;
    const int i  = site - b*NRES;

    for (int d = tid; d < DP; d += 256){
        #pragma unroll
        for (int j = 0; j < 5; j++) S.w1aT[d][j] = Wa1[j*DP + d];
        S.w1aT[d][5] = ba1[d]; S.w1aT[d][6] = 0.f; S.w1aT[d][7] = 0.f;
        #pragma unroll
        for (int j = 0; j < 3; j++) S.w1dT[d][j] = Wd1[j*DP + d];
        S.w1dT[d][3] = bd1[d];
    }
    if (tid < DP){ S.b2a[tid]=ba2[tid]; S.b2d[tid]=bd2[tid]; }
    if (tid < 3) S.tiRi[tid] = frames[(size_t)(b*NRES+i)*16 + tid*4 + 3];
    if (tid >= 32 && tid < 41){
        int e = tid - 32;
        S.tiRi[3+e] = frames[(size_t)(b*NRES+i)*16 + (e/3)*4 + (e%3)];
    }
    __syncthreads();

    const float ti0 = S.tiRi[0], ti1 = S.tiRi[1], ti2 = S.tiRi[2];
    const int   rii = ri[b*NRES + i];
    const float mi  = smask[b*NRES + i];

    #pragma unroll
    for (int e = 0; e < 3; e++){
        int j = tid*3 + e;
        const float* fj = frames + (size_t)(b*NRES + j)*16;
        float dx = fj[3]-ti0, dy = fj[7]-ti1, dz = fj[11]-ti2;
        float d = sqrtf(dx*dx + dy*dy + dz*dz);
        S.dists[j] = d;
        bool conn = abs(rii - ri[b*NRES + j]) == 1;
        bool m = (mi != 0.f) && (smask[b*NRES + j] != 0.f);
        float v = conn ? -INFV : (!m ? INFV : ((j == i) ? INFV : d));
        S.keys[j] = ((ull)okey(v) << 32) | (unsigned)j;
    }
    __syncthreads();

    if (tid < 32){
        const int lane = tid;
        ull mymin = ~0ull;
        #pragma unroll
        for (int e = 0; e < 24; e++) mymin = umin64(mymin, S.keys[e*32 + lane]);
        int mysel = -1;
        for (int it = 0; it < KTOP; it++){
            ull m = mymin;
            #pragma unroll
            for (int off = 16; off; off >>= 1)
                m = umin64(m, __shfl_xor_sync(0xffffffffu, m, off));
            if (it == lane) mysel = (int)(m & 0xffffffffu);
            if (m == mymin){
                S.keys[(int)(m & 0xffffffffu)] = ~0ull;
                ull t = ~0ull;
                #pragma unroll
                for (int e = 0; e < 24; e++) t = umin64(t, S.keys[e*32 + lane]);
                mymin = t;
            }
        }
        __syncwarp();
        if (lane < KTOP){
            int sel = mysel;
            const float* fj = frames + (size_t)(b*NRES + sel)*16;
            float dx = fj[3]-ti0, dy = fj[7]-ti1, dz = fj[11]-ti2;
            float d = S.dists[sel];
            float inv = (d > 0.f) ? (1.0f/d) : 0.f;
            float tr0 = S.tiRi[3+0]*dx + S.tiRi[3+3]*dy + S.tiRi[3+6]*dz;
            float tr1 = S.tiRi[3+1]*dx + S.tiRi[3+4]*dy + S.tiRi[3+7]*dz;
            float tr2 = S.tiRi[3+2]*dx + S.tiRi[3+5]*dy + S.tiRi[3+8]*dz;
            S.fe[0][lane] = (sel == i) ? 1.f : 0.f;
            S.fe[1][lane] = (abs(rii - ri[b*NRES + sel]) == 1) ? 1.f : 0.f;
            S.fe[2][lane] = tr0*inv;
            S.fe[3][lane] = tr1*inv;
            S.fe[4][lane] = tr2*inv;
            S.fe[5][lane] = d;
        } else {
            #pragma unroll
            for (int f = 0; f < 6; f++) S.fe[f][lane] = 0.f;
        }
    }
    __syncthreads();

    const int kk = tid & 31;
    const float f0 = S.fe[0][kk], f1 = S.fe[1][kk], f2 = S.fe[2][kk];
    const float f3 = S.fe[3][kk], f4 = S.fe[4][kk], f5 = S.fe[5][kk];
    const bool kval = (kk < KTOP);

    const int rg   = tid >> 6;           // 4 row groups (4 pairs = 8 rows)
    const int cg   = (tid >> 5) & 1;     // col half
    const int lane = tid & 31;
    const int col0 = cg*64 + lane*2;     // 2 adjacent cols per lane
    const ull* hp  = S.h2 + rg*4;
    const size_t base = (size_t)site * KTOP * DP;

    #pragma unroll
    for (int emb = 0; emb < 2; emb++){
        #pragma unroll
        for (int it = 0; it < 16; it++){
            int d = (tid >> 5) + 8*it;
            float h = 0.f;
            if (kval){
                float pre;
                if (emb == 0){
                    float4 wa = ((const float4*)S.w1aT[d])[0];
                    float4 wb = ((const float4*)S.w1aT[d])[1];
                    pre = wb.y + f0*wa.x + f1*wa.y + f2*wa.z + f3*wa.w + f4*wb.x;
                } else {
                    float4 wd = ((const float4*)S.w1dT[d])[0];
                    pre = wd.w + f0*wd.x + f1*wd.y + f5*wd.z;
                }
                h = gelu_t(pre);
            }
            ((float*)S.h2)[d*32 + kk] = h;
        }
        __syncthreads();

        const float* __restrict__ Wg = (emb ? Wd2 : Wa2) + col0;
        ull a00=0,a10=0,a20=0,a30=0, a01=0,a11=0,a21=0,a31=0;
        #pragma unroll 4
        for (int d = 0; d < DP; d++){
            F4 x0, x1;
            x0.v = ((const float4*)(hp + d*16))[0];
            x1.v = ((const float4*)(hp + d*16 + 2))[0];
            float2 w2v = *(const float2*)(Wg + d*DP);
            ull wxa = packdup(w2v.x);
            ull wxb = packdup(w2v.y);
            a00 = fma2(x0.u[0], wxa, a00); a10 = fma2(x0.u[1], wxa, a10);
            a20 = fma2(x1.u[0], wxa, a20); a30 = fma2(x1.u[1], wxa, a30);
            a01 = fma2(x0.u[0], wxb, a01); a11 = fma2(x0.u[1], wxb, a11);
            a21 = fma2(x1.u[0], wxb, a21); a31 = fma2(x1.u[1], wxb, a31);
        }
        const float* b2 = emb ? S.b2d : S.b2a;
        float bv0 = b2[col0], bv1 = b2[col0 + 1];
        float* __restrict__ og = emb ? out_dst : out_ang;
        ull accA[4] = {a00, a10, a20, a30};
        ull accB[4] = {a01, a11, a21, a31};
        #pragma unroll
        for (int p = 0; p < 4; p++){
            int r0 = rg*8 + 2*p;
            float lo, hi, lo2, hi2;
            unpack2(accA[p], lo, hi);
            unpack2(accB[p], lo2, hi2);
            if (r0 < KTOP)
                __stcs((float2*)(og + base + (size_t)r0*DP + col0), make_float2(lo + bv0, lo2 + bv1));
            if (r0 + 1 < KTOP)
                __stcs((float2*)(og + base + (size_t)(r0+1)*DP + col0), make_float2(hi + bv0, hi2 + bv1));
        }
        if (emb == 0) __syncthreads();
    }
}

// relpos: block = 2 sites, 75% TMA / 25% STG (R13-optimal split):
// site A fully TMA (768 rows); site B rows [0,384) TMA, rows [384,768) STG.128
// (evict-first streaming) issued between commit and wait.
__device__ __forceinline__ void relpos_role(
    unsigned char* smraw, int g,
    const int* __restrict__ ri,
    const float* __restrict__ W_rp, const float* __restrict__ b_rp,
    const float* __restrict__ W_tf, const float* __restrict__ b_tf,
    float* __restrict__ out_s, float* __restrict__ out_rp)
{
    SmemR& S = *reinterpret_cast<SmemR*>(smraw);
    const int tid = threadIdx.x;
    for (int e = tid; e < 65*DP; e += 256) S.T[e] = W_rp[e] + b_rp[e & 127];
    S.sv[tid] = W_tf[tid] + b_tf[tid];
    asm volatile("fence.proxy.async.shared::cta;" ::: "memory");
    __syncthreads();

    // s: 768 relpos blocks x 128 float4 = full (2,768,256)
    if (tid < 128)
        __stcs(((float4*)out_s) + g*128 + tid, ((const float4*)S.sv)[tid & 63]);

    const unsigned tsm = smem_u32(S.T);
    const int siteA = g*2, siteB = g*2 + 1;
    const int bb  = siteA / NRES;                 // both sites same batch (NRES even)
    const int iA  = siteA - bb*NRES;
    const int iB  = iA + 1;
    const int riA = ri[bb*NRES + iA];
    const int riB = ri[bb*NRES + iB];
    const int* __restrict__ rj = ri + bb*NRES;
    float* __restrict__ dstA = out_rp + (size_t)siteA * NRES * DP;
    float* __restrict__ dstB = out_rp + (size_t)siteB * NRES * DP;

    // site A: all 768 rows via TMA
    #pragma unroll
    for (int e = 0; e < 3; e++){
        int j = tid + e*256;
        int d = min(32, max(-32, riA - rj[j])) + 32;
        bulk_cp(dstA + (size_t)j*DP, tsm + (unsigned)d*512u, 512u);
    }
    // site B rows [0,384) via TMA
    {
        int j = tid;
        int d = min(32, max(-32, riB - rj[j])) + 32;
        bulk_cp(dstB + (size_t)j*DP, tsm + (unsigned)d*512u, 512u);
        if (tid < 128){
            j = 256 + tid;
            d = min(32, max(-32, riB - rj[j])) + 32;
            bulk_cp(dstB + (size_t)j*DP, tsm + (unsigned)d*512u, 512u);
        }
    }
    asm volatile("cp.async.bulk.commit_group;" ::: "memory");

    // site B rows [384,768) via streaming STG.128 while the TMA engine drains
    {
        const int lane = tid & 31;
        const int w    = tid >> 5;
        const float4* __restrict__ T4 = ((const float4*)S.T) + lane;
        float4* __restrict__ dst4 = ((float4*)dstB) + lane;
        int prevd = -1;
        float4 v;
        const int j0 = 384 + w*48;
        #pragma unroll 4
        for (int t = 0; t < 48; t++){
            int j = j0 + t;
            int d = min(32, max(-32, riB - rj[j])) + 32;
            if (d != prevd){ v = T4[d*32]; prevd = d; }
            __stcs(dst4 + (size_t)j*32, v);
        }
    }
    asm volatile("cp.async.bulk.wait_group 0;" ::: "memory");
    __syncthreads();
}

__global__ __launch_bounds__(256, 5) void fused_kernel(
    const int* __restrict__ ri, const float* __restrict__ frames, const float* __restrict__ smask,
    const float* __restrict__ W_tf, const float* __restrict__ b_tf,
    const float* __restrict__ Wa1, const float* __restrict__ ba1,
    const float* __restrict__ Wa2, const float* __restrict__ ba2,
    const float* __restrict__ Wd1, const float* __restrict__ bd1,
    const float* __restrict__ Wd2, const float* __restrict__ bd2,
    const float* __restrict__ W_rp, const float* __restrict__ b_rp,
    float* __restrict__ out_s, float* __restrict__ out_ang,
    float* __restrict__ out_dst, float* __restrict__ out_rp)
{
    extern __shared__ unsigned char smraw[];
    const int bx  = blockIdx.x;
    const int grp = bx / 6;
    const int sub = bx - grp*6;
    if (sub < 4){
        embed_role(smraw, grp*4 + sub, ri, frames, smask,
                   Wa1, ba1, Wa2, ba2, Wd1, bd1, Wd2, bd2, out_ang, out_dst);
    } else {
        relpos_role(smraw, grp*2 + (sub - 4), ri, W_rp, b_rp, W_tf, b_tf, out_s, out_rp);
    }
}

extern "C" void kernel_launch(void* const* d_in, const int* in_sizes, int n_in,
                              void* d_out, int out_size)
{
    const int*   ri     = (const int*)  d_in[1];
    const float* frames = (const float*)d_in[2];
    const float* smaskp = (const float*)d_in[3];
    const float* W_tf   = (const float*)d_in[4];
    const float* b_tf   = (const float*)d_in[5];
    const float* Wa1    = (const float*)d_in[6];
    const float* ba1    = (const float*)d_in[7];
    const float* Wa2    = (const float*)d_in[8];
    const float* ba2    = (const float*)d_in[9];
    const float* Wd1    = (const float*)d_in[10];
    const float* bd1    = (const float*)d_in[11];
    const float* Wd2    = (const float*)d_in[12];
    const float* bd2    = (const float*)d_in[13];
    const float* W_rp   = (const float*)d_in[14];
    const float* b_rp   = (const float*)d_in[15];

    float* out     = (float*)d_out;
    float* out_s   = out;                                       // (2,768,256)
    float* out_ang = out_s   + (size_t)BATCH*NRES*256;          // (2,768,30,128)
    float* out_dst = out_ang + (size_t)BATCH*NRES*KTOP*DP;      // (2,768,30,128)
    float* out_rp  = out_dst + (size_t)BATCH*NRES*KTOP*DP;      // (2,768,768,128)

    int smem = (int)(sizeof(SmemE) > sizeof(SmemR) ? sizeof(SmemE) : sizeof(SmemR));
    cudaFuncSetAttribute(fused_kernel, cudaFuncAttributeMaxDynamicSharedMemorySize, smem);

    fused_kernel<<<NGRP*6, 256, smem>>>(
        ri, frames, smaskp, W_tf, b_tf,
        Wa1, ba1, Wa2, ba2, Wd1, bd1, Wd2, bd2, W_rp, b_rp,
        out_s, out_ang, out_dst, out_rp);
}

// round 16
// speedup vs baseline: 1.0092x; 1.0088x over previous
#include <cuda_runtime.h>
#include <math.h>

#define NRES 768
#define BATCH 2
#define KTOP 30
#define DP 128
#define INFV 1e10f
#define NE   (BATCH*NRES)    // 1536 embed sites
#define NGRP 384             // groups of 6 blocks: 4 embed + 2 relpos (2 sites each)

typedef unsigned long long ull;

__device__ __forceinline__ ull fma2(ull a, ull b, ull c){
    ull d; asm("fma.rn.f32x2 %0, %1, %2, %3;" : "=l"(d) : "l"(a), "l"(b), "l"(c)); return d;
}
__device__ __forceinline__ ull packdup(float x){
    ull r; asm("mov.b64 %0, {%1, %2};" : "=l"(r) : "f"(x), "f"(x)); return r;
}
__device__ __forceinline__ void unpack2(ull v, float& lo, float& hi){
    asm("mov.b64 {%0, %1}, %2;" : "=f"(lo), "=f"(hi) : "l"(v));
}
// gelu tanh-approximate, exp-based
__device__ __forceinline__ float gelu_t(float x){
    float u = x + 0.044715f*x*x*x;
    float a = fabsf(u);
    float en = __expf(-1.5957691216057308f*a);
    float t = 1.0f - __fdividef(2.0f*en, 1.0f + en);
    return 0.5f*x*(1.0f + copysignf(t, u));
}
__device__ __forceinline__ unsigned okey(float v){
    unsigned u = __float_as_uint(v);
    return (u & 0x80000000u) ? ~u : (u | 0x80000000u);
}
__device__ __forceinline__ ull umin64(ull a, ull b){ return a < b ? a : b; }
__device__ __forceinline__ unsigned smem_u32(const void* p){
    unsigned a;
    asm("{ .reg .u64 t; cvta.to.shared.u64 t, %1; cvt.u32.u64 %0, t; }" : "=r"(a) : "l"(p));
    return a;
}
__device__ __forceinline__ void bulk_cp(void* dst, unsigned src_sm, unsigned bytes){
    asm volatile("cp.async.bulk.global.shared::cta.bulk_group [%0], [%1], %2;"
                 :: "l"(dst), "r"(src_sm), "r"(bytes) : "memory");
}

union F4 { float4 v; ull u[2]; };

struct SmemE {
    ull   h2[DP*16];      // 16 KB
    ull   keys[NRES];     // 6 KB
    float dists[NRES];    // 3 KB
    float w1aT[DP][8];    // 4 KB: [d] = {w0..w4, b1a, 0, 0}
    float w1dT[DP][4];    // 2 KB: [d] = {w0, w1, w2, b1d}
    float b2a[DP], b2d[DP];
    float fe[6][32];
};
struct SmemR {
    float T[65*DP];       // 33.3 KB relpos table (TMA + STG source)
    float sv[256];
};

__device__ __forceinline__ void embed_role(
    unsigned char* smraw, int site,
    const int* __restrict__ ri, const float* __restrict__ frames, const float* __restrict__ smask,
    const float* __restrict__ Wa1, const float* __restrict__ ba1,
    const float* __restrict__ Wa2, const float* __restrict__ ba2,
    const float* __restrict__ Wd1, const float* __restrict__ bd1,
    const float* __restrict__ Wd2, const float* __restrict__ bd2,
    float* __restrict__ out_ang, float* __restrict__ out_dst)
{
    SmemE& S = *reinterpret_cast<SmemE*>(smraw);
    const int tid = threadIdx.x;
    const int b  = site / NRES;
    const int i  = site - b*NRES;

    // phase 1: distances + keys (t_i via broadcast LDG; no staging barrier)
    const float* __restrict__ fsite = frames + (size_t)(b*NRES + i)*16;
    const float ti0 = __ldg(fsite + 3), ti1 = __ldg(fsite + 7), ti2 = __ldg(fsite + 11);
    const int   rii = ri[b*NRES + i];
    const float mi  = smask[b*NRES + i];

    #pragma unroll
    for (int e = 0; e < 3; e++){
        int j = tid*3 + e;
        const float* fj = frames + (size_t)(b*NRES + j)*16;
        float dx = fj[3]-ti0, dy = fj[7]-ti1, dz = fj[11]-ti2;
        float d = sqrtf(dx*dx + dy*dy + dz*dz);
        S.dists[j] = d;
        bool conn = abs(rii - ri[b*NRES + j]) == 1;
        bool m = (mi != 0.f) && (smask[b*NRES + j] != 0.f);
        float v = conn ? -INFV : (!m ? INFV : ((j == i) ? INFV : d));
        S.keys[j] = ((ull)okey(v) << 32) | (unsigned)j;
    }
    __syncthreads();

    // phase 2: warp0 topk+features; warps 1-7 build W1 tables concurrently
    if (tid < 32){
        const int lane = tid;
        ull mymin = ~0ull;
        #pragma unroll
        for (int e = 0; e < 24; e++) mymin = umin64(mymin, S.keys[e*32 + lane]);
        int mysel = -1;
        for (int it = 0; it < KTOP; it++){
            ull m = mymin;
            #pragma unroll
            for (int off = 16; off; off >>= 1)
                m = umin64(m, __shfl_xor_sync(0xffffffffu, m, off));
            if (it == lane) mysel = (int)(m & 0xffffffffu);
            if (m == mymin){
                S.keys[(int)(m & 0xffffffffu)] = ~0ull;
                ull t = ~0ull;
                #pragma unroll
                for (int e = 0; e < 24; e++) t = umin64(t, S.keys[e*32 + lane]);
                mymin = t;
            }
        }
        __syncwarp();
        if (lane < KTOP){
            int sel = mysel;
            const float* fj = frames + (size_t)(b*NRES + sel)*16;
            float dx = fj[3]-ti0, dy = fj[7]-ti1, dz = fj[11]-ti2;
            float d = S.dists[sel];
            float inv = (d > 0.f) ? (1.0f/d) : 0.f;
            // R row-major: R[x][y] = fsite[x*4+y]; t_rel[y] = sum_x R[x][y]*diff[x]
            float tr0 = __ldg(fsite+0)*dx + __ldg(fsite+4)*dy + __ldg(fsite+8)*dz;
            float tr1 = __ldg(fsite+1)*dx + __ldg(fsite+5)*dy + __ldg(fsite+9)*dz;
            float tr2 = __ldg(fsite+2)*dx + __ldg(fsite+6)*dy + __ldg(fsite+10)*dz;
            S.fe[0][lane] = (sel == i) ? 1.f : 0.f;
            S.fe[1][lane] = (abs(rii - ri[b*NRES + sel]) == 1) ? 1.f : 0.f;
            S.fe[2][lane] = tr0*inv;
            S.fe[3][lane] = tr1*inv;
            S.fe[4][lane] = tr2*inv;
            S.fe[5][lane] = d;
        } else {
            #pragma unroll
            for (int f = 0; f < 6; f++) S.fe[f][lane] = 0.f;
        }
    } else {
        // warps 1-7: transposed W1 tables (+bias folded) while warp0 runs topk
        for (int d = tid - 32; d < DP; d += 224){
            #pragma unroll
            for (int j = 0; j < 5; j++) S.w1aT[d][j] = Wa1[j*DP + d];
            S.w1aT[d][5] = ba1[d]; S.w1aT[d][6] = 0.f; S.w1aT[d][7] = 0.f;
            #pragma unroll
            for (int j = 0; j < 3; j++) S.w1dT[d][j] = Wd1[j*DP + d];
            S.w1dT[d][3] = bd1[d];
            S.b2a[d] = ba2[d]; S.b2d[d] = bd2[d];
        }
    }
    __syncthreads();

    const int kk = tid & 31;
    const float f0 = S.fe[0][kk], f1 = S.fe[1][kk], f2 = S.fe[2][kk];
    const float f3 = S.fe[3][kk], f4 = S.fe[4][kk], f5 = S.fe[5][kk];
    const bool kval = (kk < KTOP);

    const int rg   = tid >> 6;           // 4 row groups (4 pairs = 8 rows)
    const int cg   = (tid >> 5) & 1;     // col half
    const int lane = tid & 31;
    const int col0 = cg*64 + lane*2;     // 2 adjacent cols per lane
    const ull* hp  = S.h2 + rg*4;
    const size_t base = (size_t)site * KTOP * DP;

    #pragma unroll
    for (int emb = 0; emb < 2; emb++){
        #pragma unroll
        for (int it = 0; it < 16; it++){
            int d = (tid >> 5) + 8*it;
            float h = 0.f;
            if (kval){
                float pre;
                if (emb == 0){
                    float4 wa = ((const float4*)S.w1aT[d])[0];
                    float4 wb = ((const float4*)S.w1aT[d])[1];
                    pre = wb.y + f0*wa.x + f1*wa.y + f2*wa.z + f3*wa.w + f4*wb.x;
                } else {
                    float4 wd = ((const float4*)S.w1dT[d])[0];
                    pre = wd.w + f0*wd.x + f1*wd.y + f5*wd.z;
                }
                h = gelu_t(pre);
            }
            ((float*)S.h2)[d*32 + kk] = h;
        }
        __syncthreads();

        const float* __restrict__ Wg = (emb ? Wd2 : Wa2) + col0;
        ull a00=0,a10=0,a20=0,a30=0, a01=0,a11=0,a21=0,a31=0;
        #pragma unroll 4
        for (int d = 0; d < DP; d++){
            F4 x0, x1;
            x0.v = ((const float4*)(hp + d*16))[0];
            x1.v = ((const float4*)(hp + d*16 + 2))[0];
            float2 w2v = *(const float2*)(Wg + d*DP);
            ull wxa = packdup(w2v.x);
            ull wxb = packdup(w2v.y);
            a00 = fma2(x0.u[0], wxa, a00); a10 = fma2(x0.u[1], wxa, a10);
            a20 = fma2(x1.u[0], wxa, a20); a30 = fma2(x1.u[1], wxa, a30);
            a01 = fma2(x0.u[0], wxb, a01); a11 = fma2(x0.u[1], wxb, a11);
            a21 = fma2(x1.u[0], wxb, a21); a31 = fma2(x1.u[1], wxb, a31);
        }
        const float* b2 = emb ? S.b2d : S.b2a;
        float bv0 = b2[col0], bv1 = b2[col0 + 1];
        float* __restrict__ og = emb ? out_dst : out_ang;
        ull accA[4] = {a00, a10, a20, a30};
        ull accB[4] = {a01, a11, a21, a31};
        #pragma unroll
        for (int p = 0; p < 4; p++){
            int r0 = rg*8 + 2*p;
            float lo, hi, lo2, hi2;
            unpack2(accA[p], lo, hi);
            unpack2(accB[p], lo2, hi2);
            if (r0 < KTOP)
                *(float2*)(og + base + (size_t)r0*DP + col0) = make_float2(lo + bv0, lo2 + bv1);
            if (r0 + 1 < KTOP)
                *(float2*)(og + base + (size_t)(r0+1)*DP + col0) = make_float2(hi + bv0, hi2 + bv1);
        }
        if (emb == 0) __syncthreads();
    }
}

// relpos: block = 2 sites, 75% TMA / 25% STG (R13-optimal split):
// site A fully TMA (768 rows); site B rows [0,384) TMA, rows [384,768) STG.128
// (evict-first streaming) issued between commit and wait.
__device__ __forceinline__ void relpos_role(
    unsigned char* smraw, int g,
    const int* __restrict__ ri,
    const float* __restrict__ W_rp, const float* __restrict__ b_rp,
    const float* __restrict__ W_tf, const float* __restrict__ b_tf,
    float* __restrict__ out_s, float* __restrict__ out_rp)
{
    SmemR& S = *reinterpret_cast<SmemR*>(smraw);
    const int tid = threadIdx.x;
    for (int e = tid; e < 65*DP; e += 256) S.T[e] = W_rp[e] + b_rp[e & 127];
    S.sv[tid] = W_tf[tid] + b_tf[tid];
    asm volatile("fence.proxy.async.shared::cta;" ::: "memory");
    __syncthreads();

    // s: 768 relpos blocks x 128 float4 = full (2,768,256)
    if (tid < 128)
        __stcs(((float4*)out_s) + g*128 + tid, ((const float4*)S.sv)[tid & 63]);

    const unsigned tsm = smem_u32(S.T);
    const int siteA = g*2, siteB = g*2 + 1;
    const int bb  = siteA / NRES;                 // both sites same batch (NRES even)
    const int iA  = siteA - bb*NRES;
    const int iB  = iA + 1;
    const int riA = ri[bb*NRES + iA];
    const int riB = ri[bb*NRES + iB];
    const int* __restrict__ rj = ri + bb*NRES;
    float* __restrict__ dstA = out_rp + (size_t)siteA * NRES * DP;
    float* __restrict__ dstB = out_rp + (size_t)siteB * NRES * DP;

    // site A: all 768 rows via TMA
    #pragma unroll
    for (int e = 0; e < 3; e++){
        int j = tid + e*256;
        int d = min(32, max(-32, riA - rj[j])) + 32;
        bulk_cp(dstA + (size_t)j*DP, tsm + (unsigned)d*512u, 512u);
    }
    // site B rows [0,384) via TMA
    {
        int j = tid;
        int d = min(32, max(-32, riB - rj[j])) + 32;
        bulk_cp(dstB + (size_t)j*DP, tsm + (unsigned)d*512u, 512u);
        if (tid < 128){
            j = 256 + tid;
            d = min(32, max(-32, riB - rj[j])) + 32;
            bulk_cp(dstB + (size_t)j*DP, tsm + (unsigned)d*512u, 512u);
        }
    }
    asm volatile("cp.async.bulk.commit_group;" ::: "memory");

    // site B rows [384,768) via streaming STG.128 while the TMA engine drains
    {
        const int lane = tid & 31;
        const int w    = tid >> 5;
        const float4* __restrict__ T4 = ((const float4*)S.T) + lane;
        float4* __restrict__ dst4 = ((float4*)dstB) + lane;
        int prevd = -1;
        float4 v;
        const int j0 = 384 + w*48;
        #pragma unroll 4
        for (int t = 0; t < 48; t++){
            int j = j0 + t;
            int d = min(32, max(-32, riB - rj[j])) + 32;
            if (d != prevd){ v = T4[d*32]; prevd = d; }
            __stcs(dst4 + (size_t)j*32, v);
        }
    }
    asm volatile("cp.async.bulk.wait_group 0;" ::: "memory");
    __syncthreads();
}

__global__ __launch_bounds__(256, 5) void fused_kernel(
    const int* __restrict__ ri, const float* __restrict__ frames, const float* __restrict__ smask,
    const float* __restrict__ W_tf, const float* __restrict__ b_tf,
    const float* __restrict__ Wa1, const float* __restrict__ ba1,
    const float* __restrict__ Wa2, const float* __restrict__ ba2,
    const float* __restrict__ Wd1, const float* __restrict__ bd1,
    const float* __restrict__ Wd2, const float* __restrict__ bd2,
    const float* __restrict__ W_rp, const float* __restrict__ b_rp,
    float* __restrict__ out_s, float* __restrict__ out_ang,
    float* __restrict__ out_dst, float* __restrict__ out_rp)
{
    extern __shared__ unsigned char smraw[];
    const int bx  = blockIdx.x;
    const int grp = bx / 6;
    const int sub = bx - grp*6;
    if (sub < 4){
        embed_role(smraw, grp*4 + sub, ri, frames, smask,
                   Wa1, ba1, Wa2, ba2, Wd1, bd1, Wd2, bd2, out_ang, out_dst);
    } else {
        relpos_role(smraw, grp*2 + (sub - 4), ri, W_rp, b_rp, W_tf, b_tf, out_s, out_rp);
    }
}

extern "C" void kernel_launch(void* const* d_in, const int* in_sizes, int n_in,
                              void* d_out, int out_size)
{
    const int*   ri     = (const int*)  d_in[1];
    const float* frames = (const float*)d_in[2];
    const float* smaskp = (const float*)d_in[3];
    const float* W_tf   = (const float*)d_in[4];
    const float* b_tf   = (const float*)d_in[5];
    const float* Wa1    = (const float*)d_in[6];
    const float* ba1    = (const float*)d_in[7];
    const float* Wa2    = (const float*)d_in[8];
    const float* ba2    = (const float*)d_in[9];
    const float* Wd1    = (const float*)d_in[10];
    const float* bd1    = (const float*)d_in[11];
    const float* Wd2    = (const float*)d_in[12];
    const float* bd2    = (const float*)d_in[13];
    const float* W_rp   = (const float*)d_in[14];
    const float* b_rp   = (const float*)d_in[15];

    float* out     = (float*)d_out;
    float* out_s   = out;                                       // (2,768,256)
    float* out_ang = out_s   + (size_t)BATCH*NRES*256;          // (2,768,30,128)
    float* out_dst = out_ang + (size_t)BATCH*NRES*KTOP*DP;      // (2,768,30,128)
    float* out_rp  = out_dst + (size_t)BATCH*NRES*KTOP*DP;      // (2,768,768,128)

    int smem = (int)(sizeof(SmemE) > sizeof(SmemR) ? sizeof(SmemE) : sizeof(SmemR));
    cudaFuncSetAttribute(fused_kernel, cudaFuncAttributeMaxDynamicSharedMemorySize, smem);

    fused_kernel<<<NGRP*6, 256, smem>>>(
        ri, frames, smaskp, W_tf, b_tf,
        Wa1, ba1, Wa2, ba2, Wd1, bd1, Wd2, bd2, W_rp, b_rp,
        out_s, out_ang, out_dst, out_rp);
}

// round 17
// speedup vs baseline: 1.0101x; 1.0009x over previous
#include <cuda_runtime.h>
#include <math.h>

#define NRES 768
#define BATCH 2
#define KTOP 30
#define DP 128
#define INFV 1e10f
#define NE   (BATCH*NRES)    // 1536 embed sites
#define NGRP 384             // groups of 6 blocks: 4 embed + 2 relpos (2 sites each)

typedef unsigned long long ull;

__device__ __forceinline__ ull fma2(ull a, ull b, ull c){
    ull d; asm("fma.rn.f32x2 %0, %1, %2, %3;" : "=l"(d) : "l"(a), "l"(b), "l"(c)); return d;
}
__device__ __forceinline__ ull packdup(float x){
    ull r; asm("mov.b64 %0, {%1, %2};" : "=l"(r) : "f"(x), "f"(x)); return r;
}
__device__ __forceinline__ void unpack2(ull v, float& lo, float& hi){
    asm("mov.b64 {%0, %1}, %2;" : "=f"(lo), "=f"(hi) : "l"(v));
}
// gelu tanh-approximate, exp-based
__device__ __forceinline__ float gelu_t(float x){
    float u = x + 0.044715f*x*x*x;
    float a = fabsf(u);
    float en = __expf(-1.5957691216057308f*a);
    float t = 1.0f - __fdividef(2.0f*en, 1.0f + en);
    return 0.5f*x*(1.0f + copysignf(t, u));
}
__device__ __forceinline__ unsigned okey(float v){
    unsigned u = __float_as_uint(v);
    return (u & 0x80000000u) ? ~u : (u | 0x80000000u);
}
__device__ __forceinline__ ull umin64(ull a, ull b){ return a < b ? a : b; }
__device__ __forceinline__ unsigned smem_u32(const void* p){
    unsigned a;
    asm("{ .reg .u64 t; cvta.to.shared.u64 t, %1; cvt.u32.u64 %0, t; }" : "=r"(a) : "l"(p));
    return a;
}
__device__ __forceinline__ void bulk_cp(void* dst, unsigned src_sm, unsigned bytes){
    asm volatile("cp.async.bulk.global.shared::cta.bulk_group [%0], [%1], %2;"
                 :: "l"(dst), "r"(src_sm), "r"(bytes) : "memory");
}
// write-through streaming store (no L2 dirty-line allocation)
__device__ __forceinline__ void stwt4(float4* p, float4 v){
    asm volatile("st.global.wt.v4.f32 [%0], {%1, %2, %3, %4};"
                 :: "l"(p), "f"(v.x), "f"(v.y), "f"(v.z), "f"(v.w) : "memory");
}

union F4 { float4 v; ull u[2]; };

struct SmemE {
    ull   h2[DP*16];      // 16 KB
    ull   keys[NRES];     // 6 KB
    float dists[NRES];    // 3 KB
    float w1aT[DP][8];    // 4 KB: [d] = {w0..w4, b1a, 0, 0}
    float w1dT[DP][4];    // 2 KB: [d] = {w0, w1, w2, b1d}
    float b2a[DP], b2d[DP];
    float fe[6][32];
};
struct SmemR {
    float T[65*DP];       // 33.3 KB relpos table (TMA + STG source)
    float sv[256];
};

__device__ __forceinline__ void embed_role(
    unsigned char* smraw, int site,
    const int* __restrict__ ri, const float* __restrict__ frames, const float* __restrict__ smask,
    const float* __restrict__ Wa1, const float* __restrict__ ba1,
    const float* __restrict__ Wa2, const float* __restrict__ ba2,
    const float* __restrict__ Wd1, const float* __restrict__ bd1,
    const float* __restrict__ Wd2, const float* __restrict__ bd2,
    float* __restrict__ out_ang, float* __restrict__ out_dst)
{
    SmemE& S = *reinterpret_cast<SmemE*>(smraw);
    const int tid = threadIdx.x;
    const int b  = site / NRES;
    const int i  = site - b*NRES;

    // phase 1: distances + keys (t_i via broadcast LDG; no staging barrier)
    const float* __restrict__ fsite = frames + (size_t)(b*NRES + i)*16;
    const float ti0 = __ldg(fsite + 3), ti1 = __ldg(fsite + 7), ti2 = __ldg(fsite + 11);
    const int   rii = ri[b*NRES + i];
    const float mi  = smask[b*NRES + i];

    #pragma unroll
    for (int e = 0; e < 3; e++){
        int j = tid*3 + e;
        const float* fj = frames + (size_t)(b*NRES + j)*16;
        float dx = fj[3]-ti0, dy = fj[7]-ti1, dz = fj[11]-ti2;
        float d = sqrtf(dx*dx + dy*dy + dz*dz);
        S.dists[j] = d;
        bool conn = abs(rii - ri[b*NRES + j]) == 1;
        bool m = (mi != 0.f) && (smask[b*NRES + j] != 0.f);
        float v = conn ? -INFV : (!m ? INFV : ((j == i) ? INFV : d));
        S.keys[j] = ((ull)okey(v) << 32) | (unsigned)j;
    }
    __syncthreads();

    // phase 2: warp0 topk+features; warps 1-7 build W1 tables concurrently
    if (tid < 32){
        const int lane = tid;
        ull mymin = ~0ull;
        #pragma unroll
        for (int e = 0; e < 24; e++) mymin = umin64(mymin, S.keys[e*32 + lane]);
        int mysel = -1;
        for (int it = 0; it < KTOP; it++){
            ull m = mymin;
            #pragma unroll
            for (int off = 16; off; off >>= 1)
                m = umin64(m, __shfl_xor_sync(0xffffffffu, m, off));
            if (it == lane) mysel = (int)(m & 0xffffffffu);
            if (m == mymin){
                S.keys[(int)(m & 0xffffffffu)] = ~0ull;
                ull t = ~0ull;
                #pragma unroll
                for (int e = 0; e < 24; e++) t = umin64(t, S.keys[e*32 + lane]);
                mymin = t;
            }
        }
        __syncwarp();
        if (lane < KTOP){
            int sel = mysel;
            const float* fj = frames + (size_t)(b*NRES + sel)*16;
            float dx = fj[3]-ti0, dy = fj[7]-ti1, dz = fj[11]-ti2;
            float d = S.dists[sel];
            float inv = (d > 0.f) ? (1.0f/d) : 0.f;
            float tr0 = __ldg(fsite+0)*dx + __ldg(fsite+4)*dy + __ldg(fsite+8)*dz;
            float tr1 = __ldg(fsite+1)*dx + __ldg(fsite+5)*dy + __ldg(fsite+9)*dz;
            float tr2 = __ldg(fsite+2)*dx + __ldg(fsite+6)*dy + __ldg(fsite+10)*dz;
            S.fe[0][lane] = (sel == i) ? 1.f : 0.f;
            S.fe[1][lane] = (abs(rii - ri[b*NRES + sel]) == 1) ? 1.f : 0.f;
            S.fe[2][lane] = tr0*inv;
            S.fe[3][lane] = tr1*inv;
            S.fe[4][lane] = tr2*inv;
            S.fe[5][lane] = d;
        } else {
            #pragma unroll
            for (int f = 0; f < 6; f++) S.fe[f][lane] = 0.f;
        }
    } else {
        for (int d = tid - 32; d < DP; d += 224){
            #pragma unroll
            for (int j = 0; j < 5; j++) S.w1aT[d][j] = Wa1[j*DP + d];
            S.w1aT[d][5] = ba1[d]; S.w1aT[d][6] = 0.f; S.w1aT[d][7] = 0.f;
            #pragma unroll
            for (int j = 0; j < 3; j++) S.w1dT[d][j] = Wd1[j*DP + d];
            S.w1dT[d][3] = bd1[d];
            S.b2a[d] = ba2[d]; S.b2d[d] = bd2[d];
        }
    }
    __syncthreads();

    const int kk = tid & 31;
    const float f0 = S.fe[0][kk], f1 = S.fe[1][kk], f2 = S.fe[2][kk];
    const float f3 = S.fe[3][kk], f4 = S.fe[4][kk], f5 = S.fe[5][kk];
    const bool kval = (kk < KTOP);

    const int rg   = tid >> 6;           // 4 row groups (4 pairs = 8 rows)
    const int cg   = (tid >> 5) & 1;     // col half
    const int lane = tid & 31;
    const int col0 = cg*64 + lane*2;     // 2 adjacent cols per lane
    const ull* hp  = S.h2 + rg*4;
    const size_t base = (size_t)site * KTOP * DP;

    #pragma unroll
    for (int emb = 0; emb < 2; emb++){
        #pragma unroll
        for (int it = 0; it < 16; it++){
            int d = (tid >> 5) + 8*it;
            float h = 0.f;
            if (kval){
                float pre;
                if (emb == 0){
                    float4 wa = ((const float4*)S.w1aT[d])[0];
                    float4 wb = ((const float4*)S.w1aT[d])[1];
                    pre = wb.y + f0*wa.x + f1*wa.y + f2*wa.z + f3*wa.w + f4*wb.x;
                } else {
                    float4 wd = ((const float4*)S.w1dT[d])[0];
                    pre = wd.w + f0*wd.x + f1*wd.y + f5*wd.z;
                }
                h = gelu_t(pre);
            }
            ((float*)S.h2)[d*32 + kk] = h;
        }
        __syncthreads();

        const float* __restrict__ Wg = (emb ? Wd2 : Wa2) + col0;
        ull a00=0,a10=0,a20=0,a30=0, a01=0,a11=0,a21=0,a31=0;
        #pragma unroll 4
        for (int d = 0; d < DP; d++){
            F4 x0, x1;
            x0.v = ((const float4*)(hp + d*16))[0];
            x1.v = ((const float4*)(hp + d*16 + 2))[0];
            float2 w2v = *(const float2*)(Wg + d*DP);
            ull wxa = packdup(w2v.x);
            ull wxb = packdup(w2v.y);
            a00 = fma2(x0.u[0], wxa, a00); a10 = fma2(x0.u[1], wxa, a10);
            a20 = fma2(x1.u[0], wxa, a20); a30 = fma2(x1.u[1], wxa, a30);
            a01 = fma2(x0.u[0], wxb, a01); a11 = fma2(x0.u[1], wxb, a11);
            a21 = fma2(x1.u[0], wxb, a21); a31 = fma2(x1.u[1], wxb, a31);
        }
        const float* b2 = emb ? S.b2d : S.b2a;
        float bv0 = b2[col0], bv1 = b2[col0 + 1];
        float* __restrict__ og = emb ? out_dst : out_ang;
        ull accA[4] = {a00, a10, a20, a30};
        ull accB[4] = {a01, a11, a21, a31};
        #pragma unroll
        for (int p = 0; p < 4; p++){
            int r0 = rg*8 + 2*p;
            float lo, hi, lo2, hi2;
            unpack2(accA[p], lo, hi);
            unpack2(accB[p], lo2, hi2);
            if (r0 < KTOP)
                *(float2*)(og + base + (size_t)r0*DP + col0) = make_float2(lo + bv0, lo2 + bv1);
            if (r0 + 1 < KTOP)
                *(float2*)(og + base + (size_t)(r0+1)*DP + col0) = make_float2(hi + bv0, hi2 + bv1);
        }
        if (emb == 0) __syncthreads();
    }
}

// relpos: block = 2 sites, 75% TMA / 25% STG (optimal split):
// site A fully TMA (768 rows); site B rows [0,384) TMA, rows [384,768) via
// write-through STG.128 (no L2 dirty allocation) issued between commit and wait.
__device__ __forceinline__ void relpos_role(
    unsigned char* smraw, int g,
    const int* __restrict__ ri,
    const float* __restrict__ W_rp, const float* __restrict__ b_rp,
    const float* __restrict__ W_tf, const float* __restrict__ b_tf,
    float* __restrict__ out_s, float* __restrict__ out_rp)
{
    SmemR& S = *reinterpret_cast<SmemR*>(smraw);
    const int tid = threadIdx.x;
    for (int e = tid; e < 65*DP; e += 256) S.T[e] = W_rp[e] + b_rp[e & 127];
    S.sv[tid] = W_tf[tid] + b_tf[tid];
    asm volatile("fence.proxy.async.shared::cta;" ::: "memory");
    __syncthreads();

    // s: 768 relpos blocks x 128 float4 = full (2,768,256)
    if (tid < 128)
        ((float4*)out_s)[g*128 + tid] = ((const float4*)S.sv)[tid & 63];

    const unsigned tsm = smem_u32(S.T);
    const int siteA = g*2, siteB = g*2 + 1;
    const int bb  = siteA / NRES;                 // both sites same batch (NRES even)
    const int iA  = siteA - bb*NRES;
    const int iB  = iA + 1;
    const int riA = ri[bb*NRES + iA];
    const int riB = ri[bb*NRES + iB];
    const int* __restrict__ rj = ri + bb*NRES;
    float* __restrict__ dstA = out_rp + (size_t)siteA * NRES * DP;
    float* __restrict__ dstB = out_rp + (size_t)siteB * NRES * DP;

    // site A: all 768 rows via TMA
    #pragma unroll
    for (int e = 0; e < 3; e++){
        int j = tid + e*256;
        int d = min(32, max(-32, riA - rj[j])) + 32;
        bulk_cp(dstA + (size_t)j*DP, tsm + (unsigned)d*512u, 512u);
    }
    // site B rows [0,384) via TMA
    {
        int j = tid;
        int d = min(32, max(-32, riB - rj[j])) + 32;
        bulk_cp(dstB + (size_t)j*DP, tsm + (unsigned)d*512u, 512u);
        if (tid < 128){
            j = 256 + tid;
            d = min(32, max(-32, riB - rj[j])) + 32;
            bulk_cp(dstB + (size_t)j*DP, tsm + (unsigned)d*512u, 512u);
        }
    }
    asm volatile("cp.async.bulk.commit_group;" ::: "memory");

    // site B rows [384,768) via write-through STG.128 while the TMA engine drains
    {
        const int lane = tid & 31;
        const int w    = tid >> 5;
        const float4* __restrict__ T4 = ((const float4*)S.T) + lane;
        float4* __restrict__ dst4 = ((float4*)dstB) + lane;
        int prevd = -1;
        float4 v;
        const int j0 = 384 + w*48;
        #pragma unroll 4
        for (int t = 0; t < 48; t++){
            int j = j0 + t;
            int d = min(32, max(-32, riB - rj[j])) + 32;
            if (d != prevd){ v = T4[d*32]; prevd = d; }
            stwt4(dst4 + (size_t)j*32, v);
        }
    }
    asm volatile("cp.async.bulk.wait_group 0;" ::: "memory");
    __syncthreads();
}

__global__ __launch_bounds__(256, 5) void fused_kernel(
    const int* __restrict__ ri, const float* __restrict__ frames, const float* __restrict__ smask,
    const float* __restrict__ W_tf, const float* __restrict__ b_tf,
    const float* __restrict__ Wa1, const float* __restrict__ ba1,
    const float* __restrict__ Wa2, const float* __restrict__ ba2,
    const float* __restrict__ Wd1, const float* __restrict__ bd1,
    const float* __restrict__ Wd2, const float* __restrict__ bd2,
    const float* __restrict__ W_rp, const float* __restrict__ b_rp,
    float* __restrict__ out_s, float* __restrict__ out_ang,
    float* __restrict__ out_dst, float* __restrict__ out_rp)
{
    extern __shared__ unsigned char smraw[];
    const int bx  = blockIdx.x;
    const int grp = bx / 6;
    const int sub = bx - grp*6;
    if (sub < 4){
        embed_role(smraw, grp*4 + sub, ri, frames, smask,
                   Wa1, ba1, Wa2, ba2, Wd1, bd1, Wd2, bd2, out_ang, out_dst);
    } else {
        relpos_role(smraw, grp*2 + (sub - 4), ri, W_rp, b_rp, W_tf, b_tf, out_s, out_rp);
    }
}

extern "C" void kernel_launch(void* const* d_in, const int* in_sizes, int n_in,
                              void* d_out, int out_size)
{
    const int*   ri     = (const int*)  d_in[1];
    const float* frames = (const float*)d_in[2];
    const float* smaskp = (const float*)d_in[3];
    const float* W_tf   = (const float*)d_in[4];
    const float* b_tf   = (const float*)d_in[5];
    const float* Wa1    = (const float*)d_in[6];
    const float* ba1    = (const float*)d_in[7];
    const float* Wa2    = (const float*)d_in[8];
    const float* ba2    = (const float*)d_in[9];
    const float* Wd1    = (const float*)d_in[10];
    const float* bd1    = (const float*)d_in[11];
    const float* Wd2    = (const float*)d_in[12];
    const float* bd2    = (const float*)d_in[13];
    const float* W_rp   = (const float*)d_in[14];
    const float* b_rp   = (const float*)d_in[15];

    float* out     = (float*)d_out;
    float* out_s   = out;                                       // (2,768,256)
    float* out_ang = out_s   + (size_t)BATCH*NRES*256;          // (2,768,30,128)
    float* out_dst = out_ang + (size_t)BATCH*NRES*KTOP*DP;      // (2,768,30,128)
    float* out_rp  = out_dst + (size_t)BATCH*NRES*KTOP*DP;      // (2,768,768,128)

    int smem = (int)(sizeof(SmemE) > sizeof(SmemR) ? sizeof(SmemE) : sizeof(SmemR));
    cudaFuncSetAttribute(fused_kernel, cudaFuncAttributeMaxDynamicSharedMemorySize, smem);

    fused_kernel<<<NGRP*6, 256, smem>>>(
        ri, frames, smaskp, W_tf, b_tf,
        Wa1, ba1, Wa2, ba2, Wd1, bd1, Wd2, bd2, W_rp, b_rp,
        out_s, out_ang, out_dst, out_rp);
}